// round 3
// baseline (speedup 1.0000x reference)
#include <cuda_runtime.h>
#include <cuda_bf16.h>
#include <math.h>

// Problem dims
#define MB   256
#define RDIM 1025          // in_dim + 1 (bias row)
#define CDIM 1024
#define NSPLIT 4           // i-chunks for E-stream
#define BT   16            // batch tile for GEMM role

// Scratch (__device__ globals: allocation-free)
static __device__ float g_a[MB * RDIM];               // x1[b,i]*sr[i]
static __device__ float g_part[MB * NSPLIT * CDIM];   // E-contraction partials
static __device__ float g_gemm[MB * CDIM];            // x1 @ mu
static __device__ float g_red[128];                   // mu^2 block partials

// -------------------------------------------------------------------------
// K1: a[b,i] = x1[b,i] * exp(0.5*logvar_in[i]),  x1[b,1024] = 1
// -------------------------------------------------------------------------
__global__ __launch_bounds__(256) void k_prep(const float* __restrict__ x,
                                              const float* __restrict__ lv_in)
{
    int idx = blockIdx.x * 256 + threadIdx.x;
    if (idx >= MB * RDIM) return;
    int b = idx / RDIM;
    int i = idx - b * RDIM;
    float xv = (i < CDIM) ? x[b * CDIM + i] : 1.0f;
    g_a[idx] = xv * __expf(0.5f * lv_in[i]);
}

// -------------------------------------------------------------------------
// K2 (fused roles):
//   blocks [0, 1024):   E-stream  partial[b,chunk,o] = sum_i a[b,i]*E[b,i,o]
//   blocks [1024,1088): GEMM      g_gemm[b,o] = sum_i x1[b,i]*mu[i,o]
// -------------------------------------------------------------------------
__global__ __launch_bounds__(256) void k_main(const float* __restrict__ E,
                                              const float* __restrict__ mu,
                                              const float* __restrict__ x)
{
    __shared__ __align__(16) float xsm[BT * 128];   // [i_local][b_local], GEMM role only
    const int tid = threadIdx.x;
    const int bid = blockIdx.x;

    if (bid < MB * NSPLIT) {
        // ---------------- E-stream role ----------------
        const int b     = bid / NSPLIT;
        const int chunk = bid - b * NSPLIT;
        const int i0 = (chunk * RDIM) / NSPLIT;
        const int i1 = ((chunk + 1) * RDIM) / NSPLIT;
        const int n  = i1 - i0;

        const float* __restrict__ ap = g_a + b * RDIM + i0;
        const float* __restrict__ Ep = E + (long long)b * (RDIM * CDIM)
                                         + (long long)i0 * CDIM + (tid << 2);

        float4 c0 = make_float4(0.f,0.f,0.f,0.f);
        float4 c1 = c0, c2 = c0, c3 = c0;

        int i = 0;
        for (; i + 4 <= n; i += 4) {
            float a0 = ap[i], a1 = ap[i+1], a2 = ap[i+2], a3 = ap[i+3];
            float4 e0 = *(const float4*)(Ep + (long long)(i    ) * CDIM);
            float4 e1 = *(const float4*)(Ep + (long long)(i + 1) * CDIM);
            float4 e2 = *(const float4*)(Ep + (long long)(i + 2) * CDIM);
            float4 e3 = *(const float4*)(Ep + (long long)(i + 3) * CDIM);
            c0.x += a0*e0.x; c0.y += a0*e0.y; c0.z += a0*e0.z; c0.w += a0*e0.w;
            c1.x += a1*e1.x; c1.y += a1*e1.y; c1.z += a1*e1.z; c1.w += a1*e1.w;
            c2.x += a2*e2.x; c2.y += a2*e2.y; c2.z += a2*e2.z; c2.w += a2*e2.w;
            c3.x += a3*e3.x; c3.y += a3*e3.y; c3.z += a3*e3.z; c3.w += a3*e3.w;
        }
        for (; i < n; ++i) {
            float a0 = ap[i];
            float4 e0 = *(const float4*)(Ep + (long long)i * CDIM);
            c0.x += a0*e0.x; c0.y += a0*e0.y; c0.z += a0*e0.z; c0.w += a0*e0.w;
        }
        float4 r;
        r.x = (c0.x + c1.x) + (c2.x + c3.x);
        r.y = (c0.y + c1.y) + (c2.y + c3.y);
        r.z = (c0.z + c1.z) + (c2.z + c3.z);
        r.w = (c0.w + c1.w) + (c2.w + c3.w);
        *(float4*)(g_part + (long long)bid * CDIM + (tid << 2)) = r;
    } else {
        // ---------------- GEMM role ----------------
        const int g  = bid - MB * NSPLIT;      // 0..63
        const int bt = g >> 2;                 // 0..15
        const int ot = g & 3;                  // 0..3
        const int b0 = bt * BT;
        const int o  = ot * 256 + tid;

        float acc[BT];
        #pragma unroll
        for (int k = 0; k < BT; ++k) acc[k] = 0.f;

        for (int ic = 0; ic < RDIM; ic += 128) {
            const int len = min(128, RDIM - ic);
            // cooperative load of x1 tile, transposed: xsm[il*BT + bl]
            for (int idx = tid; idx < len * BT; idx += 256) {
                int il = idx >> 4;
                int bl = idx & (BT - 1);
                int gi = ic + il;
                xsm[idx] = (gi < CDIM) ? x[(b0 + bl) * CDIM + gi] : 1.0f;
            }
            __syncthreads();

            if (len == 128) {
                #pragma unroll 4
                for (int il = 0; il < 128; ++il) {
                    const float4* xp = (const float4*)(xsm + (il << 4));
                    float4 x0 = xp[0], x1v = xp[1], x2 = xp[2], x3 = xp[3];
                    float mv = mu[(ic + il) * CDIM + o];
                    acc[0]  += x0.x  * mv; acc[1]  += x0.y  * mv;
                    acc[2]  += x0.z  * mv; acc[3]  += x0.w  * mv;
                    acc[4]  += x1v.x * mv; acc[5]  += x1v.y * mv;
                    acc[6]  += x1v.z * mv; acc[7]  += x1v.w * mv;
                    acc[8]  += x2.x  * mv; acc[9]  += x2.y  * mv;
                    acc[10] += x2.z  * mv; acc[11] += x2.w  * mv;
                    acc[12] += x3.x  * mv; acc[13] += x3.y  * mv;
                    acc[14] += x3.z  * mv; acc[15] += x3.w  * mv;
                }
            } else {
                for (int il = 0; il < len; ++il) {
                    const float4* xp = (const float4*)(xsm + (il << 4));
                    float4 x0 = xp[0], x1v = xp[1], x2 = xp[2], x3 = xp[3];
                    float mv = mu[(ic + il) * CDIM + o];
                    acc[0]  += x0.x  * mv; acc[1]  += x0.y  * mv;
                    acc[2]  += x0.z  * mv; acc[3]  += x0.w  * mv;
                    acc[4]  += x1v.x * mv; acc[5]  += x1v.y * mv;
                    acc[6]  += x1v.z * mv; acc[7]  += x1v.w * mv;
                    acc[8]  += x2.x  * mv; acc[9]  += x2.y  * mv;
                    acc[10] += x2.z  * mv; acc[11] += x2.w  * mv;
                    acc[12] += x3.x  * mv; acc[13] += x3.y  * mv;
                    acc[14] += x3.z  * mv; acc[15] += x3.w  * mv;
                }
            }
            __syncthreads();
        }
        #pragma unroll
        for (int k = 0; k < BT; ++k)
            g_gemm[(b0 + k) * CDIM + o] = acc[k];
    }
}

// -------------------------------------------------------------------------
// K3: h[b,o] = gemm[b,o] + exp(0.5*lv_out[o]) * sum_chunk partial[b,chunk,o]
// -------------------------------------------------------------------------
__global__ __launch_bounds__(256) void k_combine(const float* __restrict__ lv_out,
                                                 float* __restrict__ out)
{
    const int b = blockIdx.x;
    const int o = threadIdx.x << 2;
    float4 p0 = *(const float4*)(g_part + ((b * NSPLIT + 0) * CDIM) + o);
    float4 p1 = *(const float4*)(g_part + ((b * NSPLIT + 1) * CDIM) + o);
    float4 p2 = *(const float4*)(g_part + ((b * NSPLIT + 2) * CDIM) + o);
    float4 p3 = *(const float4*)(g_part + ((b * NSPLIT + 3) * CDIM) + o);
    float4 gm = *(const float4*)(g_gemm + b * CDIM + o);
    float4 lv = *(const float4*)(lv_out + o);
    float4 r;
    r.x = gm.x + __expf(0.5f * lv.x) * ((p0.x + p1.x) + (p2.x + p3.x));
    r.y = gm.y + __expf(0.5f * lv.y) * ((p0.y + p1.y) + (p2.y + p3.y));
    r.z = gm.z + __expf(0.5f * lv.z) * ((p0.z + p1.z) + (p2.z + p3.z));
    r.w = gm.w + __expf(0.5f * lv.w) * ((p0.w + p1.w) + (p2.w + p3.w));
    *(float4*)(out + b * CDIM + o) = r;
}

// -------------------------------------------------------------------------
// K4: stage-1 reduction of sum(mu^2)
// -------------------------------------------------------------------------
__global__ __launch_bounds__(256) void k_dkl1(const float* __restrict__ mu)
{
    const int n = RDIM * CDIM;
    float s = 0.f;
    for (int idx = blockIdx.x * 256 + threadIdx.x; idx < n; idx += gridDim.x * 256) {
        float v = mu[idx];
        s += v * v;
    }
    // warp reduce
    for (int off = 16; off; off >>= 1)
        s += __shfl_down_sync(0xffffffffu, s, off);
    __shared__ float sm[8];
    if ((threadIdx.x & 31) == 0) sm[threadIdx.x >> 5] = s;
    __syncthreads();
    if (threadIdx.x < 8) {
        float v = sm[threadIdx.x];
        for (int off = 4; off; off >>= 1)
            v += __shfl_down_sync(0xffu, v, off);
        if (threadIdx.x == 0) g_red[blockIdx.x] = v;
    }
}

// -------------------------------------------------------------------------
// K5: finalize D_KL -> out[MB*CDIM]
// -------------------------------------------------------------------------
__global__ __launch_bounds__(256) void k_dkl2(const float* __restrict__ lv_in,
                                              const float* __restrict__ lv_out,
                                              int nblk1,
                                              float* __restrict__ out)
{
    const int tid = threadIdx.x;
    float musq = 0.f, svr = 0.f, slvi = 0.f, svc = 0.f, slvo = 0.f;
    for (int i = tid; i < nblk1; i += 256) musq += g_red[i];
    for (int i = tid; i < RDIM; i += 256) {
        float lv = lv_in[i];
        svr  += __expf(lv);
        slvi += lv;
    }
    for (int i = tid; i < CDIM; i += 256) {
        float lv = lv_out[i];
        svc  += __expf(lv);
        slvo += lv;
    }
    __shared__ float sm[5][8];
    float vals[5] = {musq, svr, slvi, svc, slvo};
    #pragma unroll
    for (int k = 0; k < 5; ++k) {
        float v = vals[k];
        for (int off = 16; off; off >>= 1)
            v += __shfl_down_sync(0xffffffffu, v, off);
        if ((tid & 31) == 0) sm[k][tid >> 5] = v;
    }
    __syncthreads();
    if (tid == 0) {
        float tot[5];
        #pragma unroll
        for (int k = 0; k < 5; ++k) {
            float v = 0.f;
            #pragma unroll
            for (int w = 0; w < 8; ++w) v += sm[k][w];
            tot[k] = v;
        }
        float dkl = 0.5f * (tot[1] * tot[3] + tot[0]
                            - (float)(RDIM) * (float)(CDIM)
                            - (float)CDIM * tot[2]
                            - (float)RDIM * tot[4]);
        out[MB * CDIM] = dkl;
    }
}

// -------------------------------------------------------------------------
extern "C" void kernel_launch(void* const* d_in, const int* in_sizes, int n_in,
                              void* d_out, int out_size)
{
    const float* x      = (const float*)d_in[0];   // (256, 1024)
    const float* mu     = (const float*)d_in[1];   // (1025, 1024)
    const float* lv_in  = (const float*)d_in[2];   // (1025,)
    const float* lv_out = (const float*)d_in[3];   // (1024,)
    const float* E      = (const float*)d_in[4];   // (256, 1025, 1024)
    float* out = (float*)d_out;                    // (256*1024 h) + 1 scalar

    k_prep<<<(MB * RDIM + 255) / 256, 256>>>(x, lv_in);
    k_main<<<MB * NSPLIT + (MB / BT) * (CDIM / 256), 256>>>(E, mu, x);
    k_combine<<<MB, 256>>>(lv_out, out);
    k_dkl1<<<112, 256>>>(mu);
    k_dkl2<<<1, 256>>>(lv_in, lv_out, 112, out);
}

// round 7
// speedup vs baseline: 1.0399x; 1.0399x over previous
#include <cuda_runtime.h>
#include <cuda_bf16.h>
#include <math.h>

// Problem dims
#define MB   256
#define RDIM 1025          // in_dim + 1 (bias row)
#define CDIM 1024
#define NSPLIT 4           // i-chunks for E-stream
#define BT   16            // batch tile for GEMM role

// Scratch (__device__ globals: allocation-free)
static __device__ float g_part[MB * NSPLIT * CDIM];   // E-contraction partials
static __device__ float g_gemm[MB * CDIM];            // x1 @ mu
static __device__ float g_red[8];                     // mu^2 partials (per ot)

// -------------------------------------------------------------------------
// K_main (fused roles):
//   blocks [0, 1024):   E-stream  partial[b,chunk,o] = sum_i a[b,i]*E[b,i,o]
//                       with a[b,i] = x1[b,i]*exp(0.5*lv_in[i]) built in smem
//   blocks [1024,1088): GEMM      g_gemm[b,o] = sum_i x1[b,i]*mu[i,o]
//                       bt==0 blocks also accumulate sum(mu^2) -> g_red[ot]
// -------------------------------------------------------------------------
__global__ __launch_bounds__(256) void k_main(const float* __restrict__ E,
                                              const float* __restrict__ mu,
                                              const float* __restrict__ x,
                                              const float* __restrict__ lv_in)
{
    __shared__ __align__(16) float smem_buf[BT * 128];   // 2048 floats, both roles
    const int tid = threadIdx.x;
    const int bid = blockIdx.x;

    if (bid < MB * NSPLIT) {
        // ---------------- E-stream role ----------------
        const int b     = bid / NSPLIT;
        const int chunk = bid - b * NSPLIT;
        const int i0 = (chunk * RDIM) / NSPLIT;
        const int i1 = ((chunk + 1) * RDIM) / NSPLIT;
        const int n  = i1 - i0;                 // 256 or 257

        // Build a[i] = x1[b,i0+i] * exp(0.5*lv_in[i0+i]) in shared memory
        #pragma unroll 1
        for (int idx = tid; idx < n; idx += 256) {
            int gi = i0 + idx;
            float xv = (gi < CDIM) ? x[b * CDIM + gi] : 1.0f;
            smem_buf[idx] = xv * __expf(0.5f * lv_in[gi]);
        }
        __syncthreads();

        // float4 view of this block's E slab; row stride = CDIM/4 = 256 float4
        const float4* __restrict__ Ep =
            (const float4*)(E + (long long)b * (RDIM * CDIM)
                              + (long long)i0 * CDIM) + tid;

        float4 c0 = make_float4(0.f,0.f,0.f,0.f);
        float4 c1 = c0, c2 = c0, c3 = c0;

        int i = 0;
        #pragma unroll 1
        for (; i + 8 <= n; i += 8) {
            // 8 independent streaming loads in flight
            float4 e0 = __ldcs(Ep + (i + 0) * 256);
            float4 e1 = __ldcs(Ep + (i + 1) * 256);
            float4 e2 = __ldcs(Ep + (i + 2) * 256);
            float4 e3 = __ldcs(Ep + (i + 3) * 256);
            float4 e4 = __ldcs(Ep + (i + 4) * 256);
            float4 e5 = __ldcs(Ep + (i + 5) * 256);
            float4 e6 = __ldcs(Ep + (i + 6) * 256);
            float4 e7 = __ldcs(Ep + (i + 7) * 256);
            float a0 = smem_buf[i + 0], a1 = smem_buf[i + 1];
            float a2 = smem_buf[i + 2], a3 = smem_buf[i + 3];
            float a4 = smem_buf[i + 4], a5 = smem_buf[i + 5];
            float a6 = smem_buf[i + 6], a7 = smem_buf[i + 7];
            c0.x += a0*e0.x; c0.y += a0*e0.y; c0.z += a0*e0.z; c0.w += a0*e0.w;
            c1.x += a1*e1.x; c1.y += a1*e1.y; c1.z += a1*e1.z; c1.w += a1*e1.w;
            c2.x += a2*e2.x; c2.y += a2*e2.y; c2.z += a2*e2.z; c2.w += a2*e2.w;
            c3.x += a3*e3.x; c3.y += a3*e3.y; c3.z += a3*e3.z; c3.w += a3*e3.w;
            c0.x += a4*e4.x; c0.y += a4*e4.y; c0.z += a4*e4.z; c0.w += a4*e4.w;
            c1.x += a5*e5.x; c1.y += a5*e5.y; c1.z += a5*e5.z; c1.w += a5*e5.w;
            c2.x += a6*e6.x; c2.y += a6*e6.y; c2.z += a6*e6.z; c2.w += a6*e6.w;
            c3.x += a7*e7.x; c3.y += a7*e7.y; c3.z += a7*e7.z; c3.w += a7*e7.w;
        }
        for (; i < n; ++i) {
            float4 e0 = __ldcs(Ep + i * 256);
            float a0 = smem_buf[i];
            c0.x += a0*e0.x; c0.y += a0*e0.y; c0.z += a0*e0.z; c0.w += a0*e0.w;
        }
        float4 r;
        r.x = (c0.x + c1.x) + (c2.x + c3.x);
        r.y = (c0.y + c1.y) + (c2.y + c3.y);
        r.z = (c0.z + c1.z) + (c2.z + c3.z);
        r.w = (c0.w + c1.w) + (c2.w + c3.w);
        *(float4*)(g_part + (long long)bid * CDIM + (tid << 2)) = r;
    } else {
        // ---------------- GEMM role ----------------
        const int g  = bid - MB * NSPLIT;      // 0..63
        const int bt = g >> 2;                 // 0..15
        const int ot = g & 3;                  // 0..3
        const int b0 = bt * BT;
        const int o  = ot * 256 + tid;

        float acc[BT];
        #pragma unroll
        for (int k = 0; k < BT; ++k) acc[k] = 0.f;
        float musq = 0.f;

        #pragma unroll 1
        for (int ic = 0; ic < RDIM; ic += 128) {
            const int len = min(128, RDIM - ic);
            // cooperative load of x1 tile, transposed: smem_buf[il*BT + bl]
            #pragma unroll 1
            for (int idx = tid; idx < len * BT; idx += 256) {
                int il = idx >> 4;
                int bl = idx & (BT - 1);
                int gi = ic + il;
                smem_buf[idx] = (gi < CDIM) ? x[(b0 + bl) * CDIM + gi] : 1.0f;
            }
            __syncthreads();

            #pragma unroll 1
            for (int il = 0; il < len; ++il) {
                const float4* xp = (const float4*)(smem_buf + (il << 4));
                float4 x0 = xp[0], x1v = xp[1], x2 = xp[2], x3 = xp[3];
                float mv = mu[(ic + il) * CDIM + o];
                musq += mv * mv;
                acc[0]  += x0.x  * mv; acc[1]  += x0.y  * mv;
                acc[2]  += x0.z  * mv; acc[3]  += x0.w  * mv;
                acc[4]  += x1v.x * mv; acc[5]  += x1v.y * mv;
                acc[6]  += x1v.z * mv; acc[7]  += x1v.w * mv;
                acc[8]  += x2.x  * mv; acc[9]  += x2.y  * mv;
                acc[10] += x2.z  * mv; acc[11] += x2.w  * mv;
                acc[12] += x3.x  * mv; acc[13] += x3.y  * mv;
                acc[14] += x3.z  * mv; acc[15] += x3.w  * mv;
            }
            __syncthreads();
        }
        #pragma unroll
        for (int k = 0; k < BT; ++k)
            g_gemm[(b0 + k) * CDIM + o] = acc[k];

        // sum(mu^2): bt==0 blocks collectively cover mu exactly once
        if (bt == 0) {
            for (int off = 16; off; off >>= 1)
                musq += __shfl_down_sync(0xffffffffu, musq, off);
            __syncthreads();
            if ((tid & 31) == 0) smem_buf[tid >> 5] = musq;
            __syncthreads();
            if (tid == 0) {
                float v = 0.f;
                #pragma unroll
                for (int w = 0; w < 8; ++w) v += smem_buf[w];
                g_red[ot] = v;
            }
        }
    }
}

// -------------------------------------------------------------------------
// K_combine: h[b,o] = gemm[b,o] + exp(0.5*lv_out[o]) * sum_chunk partial
//            block 0 additionally finalizes D_KL -> out[MB*CDIM]
// -------------------------------------------------------------------------
__global__ __launch_bounds__(256) void k_combine(const float* __restrict__ lv_in,
                                                 const float* __restrict__ lv_out,
                                                 float* __restrict__ out)
{
    const int b = blockIdx.x;
    const int o = threadIdx.x << 2;
    float4 p0 = *(const float4*)(g_part + ((b * NSPLIT + 0) * CDIM) + o);
    float4 p1 = *(const float4*)(g_part + ((b * NSPLIT + 1) * CDIM) + o);
    float4 p2 = *(const float4*)(g_part + ((b * NSPLIT + 2) * CDIM) + o);
    float4 p3 = *(const float4*)(g_part + ((b * NSPLIT + 3) * CDIM) + o);
    float4 gm = *(const float4*)(g_gemm + b * CDIM + o);
    float4 lv = *(const float4*)(lv_out + o);
    float4 r;
    r.x = gm.x + __expf(0.5f * lv.x) * ((p0.x + p1.x) + (p2.x + p3.x));
    r.y = gm.y + __expf(0.5f * lv.y) * ((p0.y + p1.y) + (p2.y + p3.y));
    r.z = gm.z + __expf(0.5f * lv.z) * ((p0.z + p1.z) + (p2.z + p3.z));
    r.w = gm.w + __expf(0.5f * lv.w) * ((p0.w + p1.w) + (p2.w + p3.w));
    *(float4*)(out + b * CDIM + o) = r;

    if (b == 0) {
        // D_KL finalize (one block, small work)
        const int tid = threadIdx.x;
        float svr = 0.f, slvi = 0.f, svc = 0.f, slvo = 0.f;
        for (int i = tid; i < RDIM; i += 256) {
            float v = lv_in[i];
            svr  += __expf(v);
            slvi += v;
        }
        for (int i = tid; i < CDIM; i += 256) {
            float v = lv_out[i];
            svc  += __expf(v);
            slvo += v;
        }
        __shared__ float sm[4][8];
        float vals[4] = {svr, slvi, svc, slvo};
        #pragma unroll
        for (int k = 0; k < 4; ++k) {
            float v = vals[k];
            for (int off = 16; off; off >>= 1)
                v += __shfl_down_sync(0xffffffffu, v, off);
            if ((tid & 31) == 0) sm[k][tid >> 5] = v;
        }
        __syncthreads();
        if (tid == 0) {
            float tot[4];
            #pragma unroll
            for (int k = 0; k < 4; ++k) {
                float v = 0.f;
                #pragma unroll
                for (int w = 0; w < 8; ++w) v += sm[k][w];
                tot[k] = v;
            }
            float musq = g_red[0] + g_red[1] + g_red[2] + g_red[3];
            float dkl = 0.5f * (tot[0] * tot[2] + musq
                                - (float)RDIM * (float)CDIM
                                - (float)CDIM * tot[1]
                                - (float)RDIM * tot[3]);
            out[MB * CDIM] = dkl;
        }
    }
}

// -------------------------------------------------------------------------
extern "C" void kernel_launch(void* const* d_in, const int* in_sizes, int n_in,
                              void* d_out, int out_size)
{
    const float* x      = (const float*)d_in[0];   // (256, 1024)
    const float* mu     = (const float*)d_in[1];   // (1025, 1024)
    const float* lv_in  = (const float*)d_in[2];   // (1025,)
    const float* lv_out = (const float*)d_in[3];   // (1024,)
    const float* E      = (const float*)d_in[4];   // (256, 1025, 1024)
    float* out = (float*)d_out;                    // (256*1024 h) + 1 scalar

    k_main<<<MB * NSPLIT + (MB / BT) * (CDIM / 256), 256>>>(E, mu, x, lv_in);
    k_combine<<<MB, 256>>>(lv_in, lv_out, out);
}